// round 12
// baseline (speedup 1.0000x reference)
#include <cuda_runtime.h>
#include <cuda_fp16.h>
#include <cstdint>

#define N_NODES 50000
#define N_EDGES 600000
#define D 128
#define NUM_LAYER 5

#define SCAN_BLK 256
#define N_SCAN_BLKS ((N_NODES + SCAN_BLK - 1) / SCAN_BLK)   // 196

// ---------------- device scratch (allocation-free) ----------------
__device__ __half g_z[N_NODES * D];        // z = h + agg, fp16  (GEMM1 A)
__device__ __half g_t[N_NODES * 2 * D];    // hidden, fp16       (GEMM2 A)
__device__ __half g_hx[N_NODES * D];       // layer io, fp16 (gather input / GEMM2 out)
__device__ int    g_cnt[N_NODES];
__device__ int    g_rowstart[N_NODES + 1];
__device__ int    g_cursor[N_NODES];
__device__ int    g_srcs[N_EDGES];
__device__ int    g_incl[N_SCAN_BLKS];
__device__ int    g_flag[N_SCAN_BLKS];
__device__ __half g_w1t[NUM_LAYER * 2 * D * D];  // [l][n=256][k=128] fp16
__device__ __half g_w2t[NUM_LAYER * 2 * D * D];  // [l][n=128][k=256] fp16

// ---------------- helpers ----------------
__device__ __forceinline__ float lrelu(float v) { return v >= 0.0f ? v : 0.2f * v; }

__device__ __forceinline__ void mma16(float* c, const uint32_t* a, const uint32_t* b) {
    asm volatile(
        "mma.sync.aligned.m16n8k16.row.col.f32.f16.f16.f32 "
        "{%0,%1,%2,%3}, {%4,%5,%6,%7}, {%8,%9}, {%0,%1,%2,%3};"
        : "+f"(c[0]), "+f"(c[1]), "+f"(c[2]), "+f"(c[3])
        : "r"(a[0]), "r"(a[1]), "r"(a[2]), "r"(a[3]), "r"(b[0]), "r"(b[1]));
}

__device__ __forceinline__ void ldsm_x4(uint32_t& r0, uint32_t& r1, uint32_t& r2,
                                        uint32_t& r3, uint32_t addr) {
    asm volatile("ldmatrix.sync.aligned.m8n8.x4.shared.b16 {%0,%1,%2,%3}, [%4];"
                 : "=r"(r0), "=r"(r1), "=r"(r2), "=r"(r3) : "r"(addr));
}

__device__ __forceinline__ uint32_t smem_u32(const void* p) {
    uint32_t a;
    asm("{ .reg .u64 t; cvta.to.shared.u64 t, %1; cvt.u32.u64 %0, t; }" : "=r"(a) : "l"(p));
    return a;
}
__device__ __forceinline__ void cp16(uint32_t s, const void* g) {
    asm volatile("cp.async.cg.shared.global [%0], [%1], 16;" :: "r"(s), "l"(g));
}
__device__ __forceinline__ void cp16z(uint32_t s, const void* g, int srcsz) {
    asm volatile("cp.async.cg.shared.global [%0], [%1], 16, %2;" :: "r"(s), "l"(g), "r"(srcsz));
}
#define CP_COMMIT() asm volatile("cp.async.commit_group;" ::: "memory")
#define CP_WAIT(n)  asm volatile("cp.async.wait_group %0;" :: "n"(n) : "memory")

// ---------------- CSR build (edge_index is int32: JAX x64 disabled) -------
__global__ void k_zero_cnt() {
    int i = blockIdx.x * blockDim.x + threadIdx.x;
    if (i < N_NODES) g_cnt[i] = 0;
    if (i < N_SCAN_BLKS) g_flag[i] = 0;
}
__global__ void k_hist(const int* __restrict__ ei) {
    int e = blockIdx.x * blockDim.x + threadIdx.x;
    if (e < N_EDGES) {
        int dst = ei[N_EDGES + e];
        if ((unsigned)dst < N_NODES) atomicAdd(&g_cnt[dst], 1);
    }
}
// single-kernel chained scan: rowstart/cursor from cnt
__global__ void k_scan1() {
    __shared__ int s[SCAN_BLK];
    __shared__ int sh_exc;
    int tid = threadIdx.x;
    int bid = blockIdx.x;
    int i = bid * SCAN_BLK + tid;
    int v = (i < N_NODES) ? g_cnt[i] : 0;
    s[tid] = v;
    __syncthreads();
#pragma unroll
    for (int off = 1; off < SCAN_BLK; off <<= 1) {
        int t = (tid >= off) ? s[tid - off] : 0;
        __syncthreads();
        s[tid] += t;
        __syncthreads();
    }
    if (tid == 0) {
        int exc = 0;
        if (bid > 0) {
            while (atomicAdd(&g_flag[bid - 1], 0) == 0) { }
            __threadfence();
            exc = g_incl[bid - 1];
        }
        g_incl[bid] = exc + s[SCAN_BLK - 1];
        __threadfence();
        atomicExch(&g_flag[bid], 1);
        sh_exc = exc;
    }
    __syncthreads();
    int exc = sh_exc;
    if (i < N_NODES) {
        int rs = exc + s[tid] - v;   // exclusive
        g_rowstart[i] = rs;
        g_cursor[i]   = rs;
    }
    if (bid == N_SCAN_BLKS - 1 && tid == SCAN_BLK - 1)
        g_rowstart[N_NODES] = exc + s[SCAN_BLK - 1];
}
__global__ void k_fill(const int* __restrict__ ei) {
    int e = blockIdx.x * blockDim.x + threadIdx.x;
    if (e < N_EDGES) {
        int src = ei[e];
        int dst = ei[N_EDGES + e];
        if ((unsigned)dst < N_NODES && (unsigned)src < N_NODES) {
            int p = atomicAdd(&g_cursor[dst], 1);
            g_srcs[p] = src;
        }
    }
}

// ------ weight transpose + fp16 convert: w[l][k][n] -> wt[l][n][k] ---------
__global__ void k_wtrans(const float* __restrict__ W1, const float* __restrict__ W2) {
    const int HALF = NUM_LAYER * 2 * D * D;   // 163840
    int i = blockIdx.x * blockDim.x + threadIdx.x;
    if (i < HALF) {
        int l = i / (2 * D * D);
        int r = i % (2 * D * D);
        int n = r / D;            // 0..255
        int k = r % D;            // 0..127
        g_w1t[i] = __float2half_rn(W1[(size_t)l * 2 * D * D + (size_t)k * (2 * D) + n]);
    } else if (i < 2 * HALF) {
        int j = i - HALF;
        int l = j / (2 * D * D);
        int r = j % (2 * D * D);
        int n = r / (2 * D);      // 0..127
        int k = r % (2 * D);      // 0..255
        g_w2t[j] = __float2half_rn(W2[(size_t)l * 2 * D * D + (size_t)k * D + n]);
    }
}

// ------ x (f32) -> fp16 conversion (first-layer gather input) --------------
__global__ void k_xconv(const float* __restrict__ x, __half* __restrict__ xh) {
    int i = blockIdx.x * blockDim.x + threadIdx.x;   // over N*D/4
    if (i < N_NODES * D / 4) {
        float4 v = __ldg(&((const float4*)x)[i]);
        __half2 p0 = make_half2(__float2half_rn(v.x), __float2half_rn(v.y));
        __half2 p1 = make_half2(__float2half_rn(v.z), __float2half_rn(v.w));
        uint2 pk;
        pk.x = *(uint32_t*)&p0;
        pk.y = *(uint32_t*)&p1;
        ((uint2*)xh)[i] = pk;
    }
}

// ------ gather (fp16 in/out, fp32 accum): z[n] = h[n] + sum h[src] ---------
__global__ void k_gather16(const __half* __restrict__ h, __half* __restrict__ z) {
    int warp = (blockIdx.x * blockDim.x + threadIdx.x) >> 5;
    int lane = threadIdx.x & 31;
    if (warp >= N_NODES) return;
    const uint2* hv = (const uint2*)h;     // 4 halfs per uint2; 32 uint2 per row
    int s0 = g_rowstart[warp];
    int s1 = g_rowstart[warp + 1];

    uint2 u = __ldg(&hv[(size_t)warp * 32 + lane]);
    float2 a0 = __half22float2(*(__half2*)&u.x);
    float2 a1 = __half22float2(*(__half2*)&u.y);
    float ax = a0.x, ay = a0.y, az = a1.x, aw = a1.y;

    int e = s0;
    for (; e + 3 < s1; e += 4) {
        int sa = g_srcs[e],     sb = g_srcs[e + 1];
        int sc = g_srcs[e + 2], sd = g_srcs[e + 3];
        uint2 va = __ldg(&hv[(size_t)sa * 32 + lane]);
        uint2 vb = __ldg(&hv[(size_t)sb * 32 + lane]);
        uint2 vc = __ldg(&hv[(size_t)sc * 32 + lane]);
        uint2 vd = __ldg(&hv[(size_t)sd * 32 + lane]);
        float2 fa0 = __half22float2(*(__half2*)&va.x), fa1 = __half22float2(*(__half2*)&va.y);
        float2 fb0 = __half22float2(*(__half2*)&vb.x), fb1 = __half22float2(*(__half2*)&vb.y);
        float2 fc0 = __half22float2(*(__half2*)&vc.x), fc1 = __half22float2(*(__half2*)&vc.y);
        float2 fd0 = __half22float2(*(__half2*)&vd.x), fd1 = __half22float2(*(__half2*)&vd.y);
        ax += (fa0.x + fb0.x) + (fc0.x + fd0.x);
        ay += (fa0.y + fb0.y) + (fc0.y + fd0.y);
        az += (fa1.x + fb1.x) + (fc1.x + fd1.x);
        aw += (fa1.y + fb1.y) + (fc1.y + fd1.y);
    }
    for (; e < s1; e++) {
        int sa = g_srcs[e];
        uint2 va = __ldg(&hv[(size_t)sa * 32 + lane]);
        float2 fa0 = __half22float2(*(__half2*)&va.x), fa1 = __half22float2(*(__half2*)&va.y);
        ax += fa0.x; ay += fa0.y; az += fa1.x; aw += fa1.y;
    }
    __half2 p0 = make_half2(__float2half_rn(ax), __float2half_rn(ay));
    __half2 p1 = make_half2(__float2half_rn(az), __float2half_rn(aw));
    uint2 pk;
    pk.x = *(uint32_t*)&p0;
    pk.y = *(uint32_t*)&p1;
    ((uint2*)z)[(size_t)warp * 32 + lane] = pk;
}

// ---------------- fp16 mma.sync GEMM, cp.async staged, ldmatrix frags ------
// C = act(A[M,K] @ Bt[N,K]^T + bias). Block 128x128, 8 warps (4x2), warp 32x64.
// BK=64, 2-stage cp.async pipeline. A fp16 [M][K], Bt fp16 [N][K].
// MODE: 0 = f32 out, no act; 2 = fp16 out, leaky
template <int K, int N, int MODE>
__global__ __launch_bounds__(256) void k_gemm(
    const __half* __restrict__ A, const __half* __restrict__ Bt,
    const float* __restrict__ bias, void* __restrict__ Cv)
{
    const int M = N_NODES;
    const int BK = 64;
    const int CHUNKS = K / BK;
    const int STRIDE = 72;                  // halfs per row (64 + 8 pad), 144B
    const int TILE = 128 * STRIDE;

    extern __shared__ __half sh[];
    __half* Asb[2] = { sh, sh + TILE };
    __half* Bsb[2] = { sh + 2 * TILE, sh + 3 * TILE };

    int tid  = threadIdx.x;
    int warp = tid >> 5;
    int lane = tid & 31;
    int wm = warp >> 1;
    int wn = warp & 1;
    int g  = lane >> 2;
    int tg = lane & 3;
    int m0 = blockIdx.x * 128;
    int n0 = blockIdx.y * 128;

    uint32_t asb32[2] = { smem_u32(Asb[0]), smem_u32(Asb[1]) };
    uint32_t bsb32[2] = { smem_u32(Bsb[0]), smem_u32(Bsb[1]) };

    // ldmatrix lane offsets (in halfs, before +kk)
    int quad = lane >> 3, rin = lane & 7;
    int a_off[2], b_off[4];
#pragma unroll
    for (int mt = 0; mt < 2; mt++)
        a_off[mt] = (wm * 32 + mt * 16 + (quad & 1) * 8 + rin) * STRIDE + (quad >> 1) * 8;
#pragma unroll
    for (int ntp = 0; ntp < 4; ntp++)
        b_off[ntp] = (wn * 64 + ntp * 16 + (quad >> 1) * 8 + rin) * STRIDE + (quad & 1) * 8;

    auto stage = [&](int ch, int buf) {
        uint32_t abase = asb32[buf];
        uint32_t bbase = bsb32[buf];
#pragma unroll
        for (int j = 0; j < 4; j++) {
            int seg = tid + j * 256;
            int r   = seg >> 3;
            int c16 = seg & 7;
            int gr  = m0 + r;
            uint32_t dst = abase + (uint32_t)(r * STRIDE * 2 + c16 * 16);
            const __half* src = &A[(size_t)gr * K + ch * BK + c16 * 8];
            cp16z(dst, src, (gr < M) ? 16 : 0);
        }
#pragma unroll
        for (int j = 0; j < 4; j++) {
            int seg = tid + j * 256;
            int r   = seg >> 3;
            int c16 = seg & 7;
            uint32_t dst = bbase + (uint32_t)(r * STRIDE * 2 + c16 * 16);
            const __half* src = &Bt[(size_t)(n0 + r) * K + ch * BK + c16 * 8];
            cp16(dst, src);
        }
        CP_COMMIT();
    };

    stage(0, 0);
    if (CHUNKS > 1) stage(1, 1);

    float acc[2][8][4];
#pragma unroll
    for (int a = 0; a < 2; a++)
#pragma unroll
        for (int b = 0; b < 8; b++)
#pragma unroll
            for (int c = 0; c < 4; c++) acc[a][b][c] = 0.0f;

#pragma unroll
    for (int ch = 0; ch < CHUNKS; ch++) {
        const int buf = ch & 1;
        if (ch + 1 < CHUNKS) { CP_WAIT(1); } else { CP_WAIT(0); }
        __syncthreads();

        uint32_t abase = asb32[buf];
        uint32_t bbase = bsb32[buf];
#pragma unroll
        for (int kk = 0; kk < BK; kk += 16) {
            uint32_t af[2][4], bf[8][2];
#pragma unroll
            for (int mt = 0; mt < 2; mt++)
                ldsm_x4(af[mt][0], af[mt][1], af[mt][2], af[mt][3],
                        abase + (uint32_t)(a_off[mt] + kk) * 2);
#pragma unroll
            for (int ntp = 0; ntp < 4; ntp++)
                ldsm_x4(bf[2 * ntp][0], bf[2 * ntp][1], bf[2 * ntp + 1][0], bf[2 * ntp + 1][1],
                        bbase + (uint32_t)(b_off[ntp] + kk) * 2);
#pragma unroll
            for (int mt = 0; mt < 2; mt++)
#pragma unroll
                for (int nt = 0; nt < 8; nt++)
                    mma16(acc[mt][nt], af[mt], bf[nt]);
        }
        __syncthreads();
        if (ch + 2 < CHUNKS) stage(ch + 2, buf);
    }

    // epilogue
#pragma unroll
    for (int mt = 0; mt < 2; mt++) {
#pragma unroll
        for (int nt = 0; nt < 8; nt++) {
            int row = m0 + wm * 32 + mt * 16 + g;
            int col = n0 + wn * 64 + nt * 8 + 2 * tg;
            float b0 = __ldg(&bias[col]);
            float b1 = __ldg(&bias[col + 1]);
            float v0 = acc[mt][nt][0] + b0;
            float v1 = acc[mt][nt][1] + b1;
            float v2 = acc[mt][nt][2] + b0;
            float v3 = acc[mt][nt][3] + b1;
            if (MODE >= 1) {
                v0 = lrelu(v0); v1 = lrelu(v1);
                v2 = lrelu(v2); v3 = lrelu(v3);
            }
            if (MODE == 2) {
                __half* C = (__half*)Cv;
                __half2 pa = make_half2(__float2half_rn(v0), __float2half_rn(v1));
                __half2 pb = make_half2(__float2half_rn(v2), __float2half_rn(v3));
                if (row < M)     *(uint32_t*)&C[(size_t)row * N + col]       = *(uint32_t*)&pa;
                if (row + 8 < M) *(uint32_t*)&C[(size_t)(row + 8) * N + col] = *(uint32_t*)&pb;
            } else {
                float* C = (float*)Cv;
                if (row < M)     *(float2*)&C[(size_t)row * N + col]       = make_float2(v0, v1);
                if (row + 8 < M) *(float2*)&C[(size_t)(row + 8) * N + col] = make_float2(v2, v3);
            }
        }
    }
}

// ---------------- launch ----------------
extern "C" void kernel_launch(void* const* d_in, const int* in_sizes, int n_in,
                              void* d_out, int out_size) {
    const float* x  = (const float*)d_in[0];
    const int*   ei = (const int*)d_in[1];     // int32 (JAX x64 disabled)
    const float* W1 = (const float*)d_in[2];
    const float* b1 = (const float*)d_in[3];
    const float* W2 = (const float*)d_in[4];
    const float* b2 = (const float*)d_in[5];
    float*       out = (float*)d_out;

    __half *zp, *tp, *hxp, *w1t, *w2t;
    cudaGetSymbolAddress((void**)&zp, g_z);
    cudaGetSymbolAddress((void**)&tp, g_t);
    cudaGetSymbolAddress((void**)&hxp, g_hx);
    cudaGetSymbolAddress((void**)&w1t, g_w1t);
    cudaGetSymbolAddress((void**)&w2t, g_w2t);

    const int SMEM = 4 * 128 * 72 * 2;   // 73728 B
    cudaFuncSetAttribute(k_gemm<128, 256, 2>, cudaFuncAttributeMaxDynamicSharedMemorySize, SMEM);
    cudaFuncSetAttribute(k_gemm<256, 128, 2>, cudaFuncAttributeMaxDynamicSharedMemorySize, SMEM);
    cudaFuncSetAttribute(k_gemm<256, 128, 0>, cudaFuncAttributeMaxDynamicSharedMemorySize, SMEM);

    const int M = N_NODES;
    const int MB = (M + 127) / 128;            // 391
    dim3 blk(256);
    dim3 grid_gather((N_NODES * 32 + 255) / 256);
    dim3 grid_g1(MB, 2);    // N=256, BN=128
    dim3 grid_g2(MB, 1);    // N=128, BN=128

    // launch order chosen so the 6th launch (ncu -s 5 -c 1) is k_gather16
    k_zero_cnt<<<(N_NODES + 255) / 256, 256>>>();                      // 1
    k_hist<<<(N_EDGES + 255) / 256, 256>>>(ei);                        // 2
    k_scan1<<<N_SCAN_BLKS, SCAN_BLK>>>();                              // 3
    k_fill<<<(N_EDGES + 255) / 256, 256>>>(ei);                        // 4
    k_xconv<<<(N_NODES * D / 4 + 255) / 256, 256>>>(x, hxp);           // 5
    k_gather16<<<grid_gather, blk>>>(hxp, zp);                         // 6  <- profiled
    k_wtrans<<<(2 * NUM_LAYER * 2 * D * D + 255) / 256, 256>>>(W1, W2);// 7

    for (int l = 0; l < NUM_LAYER; l++) {
        if (l > 0) k_gather16<<<grid_gather, blk>>>(hxp, zp);
        k_gemm<128, 256, 2><<<grid_g1, blk, SMEM>>>(zp, w1t + (size_t)l * 2 * D * D,
                                                    b1 + (size_t)l * 2 * D, (void*)tp);
        if (l < NUM_LAYER - 1)
            k_gemm<256, 128, 2><<<grid_g2, blk, SMEM>>>(tp, w2t + (size_t)l * 2 * D * D,
                                                        b2 + (size_t)l * D, (void*)hxp);
        else
            k_gemm<256, 128, 0><<<grid_g2, blk, SMEM>>>(tp, w2t + (size_t)l * 2 * D * D,
                                                        b2 + (size_t)l * D, (void*)out);
    }
}

// round 13
// speedup vs baseline: 1.8296x; 1.8296x over previous
#include <cuda_runtime.h>
#include <cuda_fp16.h>
#include <cstdint>

#define N_NODES 50000
#define N_EDGES 600000
#define D 128
#define NUM_LAYER 5

#define SCAN_BLK 256
#define N_SCAN_BLKS ((N_NODES + SCAN_BLK - 1) / SCAN_BLK)   // 196

// ---------------- device scratch (allocation-free) ----------------
__device__ __half g_z[N_NODES * D];        // z = h + agg, fp16  (GEMM1 A)
__device__ __half g_t[N_NODES * 2 * D];    // hidden, fp16       (GEMM2 A)
__device__ __half g_hx[N_NODES * D];       // layer io, fp16 (gather input / GEMM2 out)
__device__ int    g_cnt[N_NODES];
__device__ int    g_rowstart[N_NODES + 1];
__device__ int    g_cursor[N_NODES];
__device__ int    g_srcs[N_EDGES];
__device__ int    g_blksum[N_SCAN_BLKS];
__device__ __half g_w1t[NUM_LAYER * 2 * D * D];  // [l][n=256][k=128] fp16
__device__ __half g_w2t[NUM_LAYER * 2 * D * D];  // [l][n=128][k=256] fp16

// ---------------- helpers ----------------
__device__ __forceinline__ float lrelu(float v) { return v >= 0.0f ? v : 0.2f * v; }

__device__ __forceinline__ void mma16(float* c, const uint32_t* a, const uint32_t* b) {
    asm volatile(
        "mma.sync.aligned.m16n8k16.row.col.f32.f16.f16.f32 "
        "{%0,%1,%2,%3}, {%4,%5,%6,%7}, {%8,%9}, {%0,%1,%2,%3};"
        : "+f"(c[0]), "+f"(c[1]), "+f"(c[2]), "+f"(c[3])
        : "r"(a[0]), "r"(a[1]), "r"(a[2]), "r"(a[3]), "r"(b[0]), "r"(b[1]));
}

__device__ __forceinline__ void ldsm_x4(uint32_t& r0, uint32_t& r1, uint32_t& r2,
                                        uint32_t& r3, uint32_t addr) {
    asm volatile("ldmatrix.sync.aligned.m8n8.x4.shared.b16 {%0,%1,%2,%3}, [%4];"
                 : "=r"(r0), "=r"(r1), "=r"(r2), "=r"(r3) : "r"(addr));
}

__device__ __forceinline__ uint32_t smem_u32(const void* p) {
    uint32_t a;
    asm("{ .reg .u64 t; cvta.to.shared.u64 t, %1; cvt.u32.u64 %0, t; }" : "=r"(a) : "l"(p));
    return a;
}
__device__ __forceinline__ void cp16(uint32_t s, const void* g) {
    asm volatile("cp.async.cg.shared.global [%0], [%1], 16;" :: "r"(s), "l"(g));
}
__device__ __forceinline__ void cp16z(uint32_t s, const void* g, int srcsz) {
    asm volatile("cp.async.cg.shared.global [%0], [%1], 16, %2;" :: "r"(s), "l"(g), "r"(srcsz));
}
#define CP_COMMIT() asm volatile("cp.async.commit_group;" ::: "memory")
#define CP_WAIT(n)  asm volatile("cp.async.wait_group %0;" :: "n"(n) : "memory")

// ------ fused setup: zero cnt, x->fp16, weight transpose+convert -----------
__global__ void k_setup(const float* __restrict__ x,
                        const float* __restrict__ W1, const float* __restrict__ W2) {
    const int HALF = NUM_LAYER * 2 * D * D;   // 163840
    int i = blockIdx.x * blockDim.x + threadIdx.x;
    if (i < N_NODES) g_cnt[i] = 0;
    if (i < N_NODES * D / 4) {
        float4 v = __ldg(&((const float4*)x)[i]);
        __half2 p0 = make_half2(__float2half_rn(v.x), __float2half_rn(v.y));
        __half2 p1 = make_half2(__float2half_rn(v.z), __float2half_rn(v.w));
        uint2 pk;
        pk.x = *(uint32_t*)&p0;
        pk.y = *(uint32_t*)&p1;
        ((uint2*)g_hx)[i] = pk;
    }
    if (i < HALF) {
        int l = i / (2 * D * D);
        int r = i % (2 * D * D);
        int n = r / D;            // 0..255
        int k = r % D;            // 0..127
        g_w1t[i] = __float2half_rn(W1[(size_t)l * 2 * D * D + (size_t)k * (2 * D) + n]);
        int n2 = r / (2 * D);     // 0..127
        int k2 = r % (2 * D);     // 0..255
        g_w2t[i] = __float2half_rn(W2[(size_t)l * 2 * D * D + (size_t)k2 * D + n2]);
    }
}

__global__ void k_hist(const int* __restrict__ ei) {
    int e = blockIdx.x * blockDim.x + threadIdx.x;
    if (e < N_EDGES) {
        int dst = ei[N_EDGES + e];
        if ((unsigned)dst < N_NODES) atomicAdd(&g_cnt[dst], 1);
    }
}

// scan phase 1: per-block sums of g_cnt
__global__ void k_blocksum() {
    __shared__ int s[SCAN_BLK];
    int tid = threadIdx.x;
    int i = blockIdx.x * SCAN_BLK + tid;
    int v = (i < N_NODES) ? g_cnt[i] : 0;
    s[tid] = v;
    __syncthreads();
#pragma unroll
    for (int off = SCAN_BLK / 2; off > 0; off >>= 1) {
        if (tid < off) s[tid] += s[tid + off];
        __syncthreads();
    }
    if (tid == 0) g_blksum[blockIdx.x] = s[0];
}

// scan phase 2: each block scans the 196 block sums redundantly (parallel,
// no cross-block dependency), then local exclusive scan -> rowstart/cursor
__global__ void k_scatter2() {
    __shared__ int bs[256];
    __shared__ int s[SCAN_BLK];
    int tid = threadIdx.x;
    int bid = blockIdx.x;
    // inclusive scan of block sums
    int bv = (tid < N_SCAN_BLKS) ? g_blksum[tid] : 0;
    bs[tid] = bv;
    __syncthreads();
#pragma unroll
    for (int off = 1; off < 256; off <<= 1) {
        int t = (tid >= off) ? bs[tid - off] : 0;
        __syncthreads();
        bs[tid] += t;
        __syncthreads();
    }
    int exc_blk = (bid > 0) ? bs[bid - 1] : 0;
    // local scan
    int i = bid * SCAN_BLK + tid;
    int v = (i < N_NODES) ? g_cnt[i] : 0;
    s[tid] = v;
    __syncthreads();
#pragma unroll
    for (int off = 1; off < SCAN_BLK; off <<= 1) {
        int t = (tid >= off) ? s[tid - off] : 0;
        __syncthreads();
        s[tid] += t;
        __syncthreads();
    }
    if (i < N_NODES) {
        int rs = exc_blk + s[tid] - v;   // exclusive
        g_rowstart[i] = rs;
        g_cursor[i]   = rs;
    }
    if (bid == N_SCAN_BLKS - 1 && tid == 255)
        g_rowstart[N_NODES] = bs[N_SCAN_BLKS - 1];
}

__global__ void k_fill(const int* __restrict__ ei) {
    int e = blockIdx.x * blockDim.x + threadIdx.x;
    if (e < N_EDGES) {
        int src = ei[e];
        int dst = ei[N_EDGES + e];
        if ((unsigned)dst < N_NODES && (unsigned)src < N_NODES) {
            int p = atomicAdd(&g_cursor[dst], 1);
            g_srcs[p] = src;
        }
    }
}

// ------ gather (fp16 in/out, fp32 accum): z[n] = h[n] + sum h[src] ---------
__global__ void k_gather16(const __half* __restrict__ h, __half* __restrict__ z) {
    int warp = (blockIdx.x * blockDim.x + threadIdx.x) >> 5;
    int lane = threadIdx.x & 31;
    if (warp >= N_NODES) return;
    const uint2* hv = (const uint2*)h;     // 4 halfs per uint2; 32 uint2 per row
    int s0 = g_rowstart[warp];
    int s1 = g_rowstart[warp + 1];

    uint2 u = __ldg(&hv[(size_t)warp * 32 + lane]);
    float2 a0 = __half22float2(*(__half2*)&u.x);
    float2 a1 = __half22float2(*(__half2*)&u.y);
    float ax = a0.x, ay = a0.y, az = a1.x, aw = a1.y;

    int e = s0;
    for (; e + 3 < s1; e += 4) {
        int sa = g_srcs[e],     sb = g_srcs[e + 1];
        int sc = g_srcs[e + 2], sd = g_srcs[e + 3];
        uint2 va = __ldg(&hv[(size_t)sa * 32 + lane]);
        uint2 vb = __ldg(&hv[(size_t)sb * 32 + lane]);
        uint2 vc = __ldg(&hv[(size_t)sc * 32 + lane]);
        uint2 vd = __ldg(&hv[(size_t)sd * 32 + lane]);
        float2 fa0 = __half22float2(*(__half2*)&va.x), fa1 = __half22float2(*(__half2*)&va.y);
        float2 fb0 = __half22float2(*(__half2*)&vb.x), fb1 = __half22float2(*(__half2*)&vb.y);
        float2 fc0 = __half22float2(*(__half2*)&vc.x), fc1 = __half22float2(*(__half2*)&vc.y);
        float2 fd0 = __half22float2(*(__half2*)&vd.x), fd1 = __half22float2(*(__half2*)&vd.y);
        ax += (fa0.x + fb0.x) + (fc0.x + fd0.x);
        ay += (fa0.y + fb0.y) + (fc0.y + fd0.y);
        az += (fa1.x + fb1.x) + (fc1.x + fd1.x);
        aw += (fa1.y + fb1.y) + (fc1.y + fd1.y);
    }
    for (; e < s1; e++) {
        int sa = g_srcs[e];
        uint2 va = __ldg(&hv[(size_t)sa * 32 + lane]);
        float2 fa0 = __half22float2(*(__half2*)&va.x), fa1 = __half22float2(*(__half2*)&va.y);
        ax += fa0.x; ay += fa0.y; az += fa1.x; aw += fa1.y;
    }
    __half2 p0 = make_half2(__float2half_rn(ax), __float2half_rn(ay));
    __half2 p1 = make_half2(__float2half_rn(az), __float2half_rn(aw));
    uint2 pk;
    pk.x = *(uint32_t*)&p0;
    pk.y = *(uint32_t*)&p1;
    ((uint2*)z)[(size_t)warp * 32 + lane] = pk;
}

// ---------------- fp16 mma.sync GEMM, cp.async staged, ldmatrix frags ------
// C = act(A[M,K] @ Bt[N,K]^T + bias). Block 128x128, 8 warps (4x2), warp 32x64.
// BK=64, 2-stage cp.async pipeline. A fp16 [M][K], Bt fp16 [N][K].
// MODE: 0 = f32 out, no act; 2 = fp16 out, leaky
template <int K, int N, int MODE>
__global__ __launch_bounds__(256) void k_gemm(
    const __half* __restrict__ A, const __half* __restrict__ Bt,
    const float* __restrict__ bias, void* __restrict__ Cv)
{
    const int M = N_NODES;
    const int BK = 64;
    const int CHUNKS = K / BK;
    const int STRIDE = 72;                  // halfs per row (64 + 8 pad), 144B
    const int TILE = 128 * STRIDE;

    extern __shared__ __half sh[];
    __half* Asb[2] = { sh, sh + TILE };
    __half* Bsb[2] = { sh + 2 * TILE, sh + 3 * TILE };

    int tid  = threadIdx.x;
    int warp = tid >> 5;
    int lane = tid & 31;
    int wm = warp >> 1;
    int wn = warp & 1;
    int g  = lane >> 2;
    int tg = lane & 3;
    int m0 = blockIdx.x * 128;
    int n0 = blockIdx.y * 128;

    uint32_t asb32[2] = { smem_u32(Asb[0]), smem_u32(Asb[1]) };
    uint32_t bsb32[2] = { smem_u32(Bsb[0]), smem_u32(Bsb[1]) };

    // ldmatrix lane offsets (in halfs, before +kk)
    int quad = lane >> 3, rin = lane & 7;
    int a_off[2], b_off[4];
#pragma unroll
    for (int mt = 0; mt < 2; mt++)
        a_off[mt] = (wm * 32 + mt * 16 + (quad & 1) * 8 + rin) * STRIDE + (quad >> 1) * 8;
#pragma unroll
    for (int ntp = 0; ntp < 4; ntp++)
        b_off[ntp] = (wn * 64 + ntp * 16 + (quad >> 1) * 8 + rin) * STRIDE + (quad & 1) * 8;

    auto stage = [&](int ch, int buf) {
        uint32_t abase = asb32[buf];
        uint32_t bbase = bsb32[buf];
#pragma unroll
        for (int j = 0; j < 4; j++) {
            int seg = tid + j * 256;
            int r   = seg >> 3;
            int c16 = seg & 7;
            int gr  = m0 + r;
            uint32_t dst = abase + (uint32_t)(r * STRIDE * 2 + c16 * 16);
            const __half* src = &A[(size_t)gr * K + ch * BK + c16 * 8];
            cp16z(dst, src, (gr < M) ? 16 : 0);
        }
#pragma unroll
        for (int j = 0; j < 4; j++) {
            int seg = tid + j * 256;
            int r   = seg >> 3;
            int c16 = seg & 7;
            uint32_t dst = bbase + (uint32_t)(r * STRIDE * 2 + c16 * 16);
            const __half* src = &Bt[(size_t)(n0 + r) * K + ch * BK + c16 * 8];
            cp16(dst, src);
        }
        CP_COMMIT();
    };

    stage(0, 0);
    if (CHUNKS > 1) stage(1, 1);

    float acc[2][8][4];
#pragma unroll
    for (int a = 0; a < 2; a++)
#pragma unroll
        for (int b = 0; b < 8; b++)
#pragma unroll
            for (int c = 0; c < 4; c++) acc[a][b][c] = 0.0f;

#pragma unroll
    for (int ch = 0; ch < CHUNKS; ch++) {
        const int buf = ch & 1;
        if (ch + 1 < CHUNKS) { CP_WAIT(1); } else { CP_WAIT(0); }
        __syncthreads();

        uint32_t abase = asb32[buf];
        uint32_t bbase = bsb32[buf];
#pragma unroll
        for (int kk = 0; kk < BK; kk += 16) {
            uint32_t af[2][4], bf[8][2];
#pragma unroll
            for (int mt = 0; mt < 2; mt++)
                ldsm_x4(af[mt][0], af[mt][1], af[mt][2], af[mt][3],
                        abase + (uint32_t)(a_off[mt] + kk) * 2);
#pragma unroll
            for (int ntp = 0; ntp < 4; ntp++)
                ldsm_x4(bf[2 * ntp][0], bf[2 * ntp][1], bf[2 * ntp + 1][0], bf[2 * ntp + 1][1],
                        bbase + (uint32_t)(b_off[ntp] + kk) * 2);
#pragma unroll
            for (int mt = 0; mt < 2; mt++)
#pragma unroll
                for (int nt = 0; nt < 8; nt++)
                    mma16(acc[mt][nt], af[mt], bf[nt]);
        }
        __syncthreads();
        if (ch + 2 < CHUNKS) stage(ch + 2, buf);
    }

    // epilogue
#pragma unroll
    for (int mt = 0; mt < 2; mt++) {
#pragma unroll
        for (int nt = 0; nt < 8; nt++) {
            int row = m0 + wm * 32 + mt * 16 + g;
            int col = n0 + wn * 64 + nt * 8 + 2 * tg;
            float b0 = __ldg(&bias[col]);
            float b1 = __ldg(&bias[col + 1]);
            float v0 = acc[mt][nt][0] + b0;
            float v1 = acc[mt][nt][1] + b1;
            float v2 = acc[mt][nt][2] + b0;
            float v3 = acc[mt][nt][3] + b1;
            if (MODE >= 1) {
                v0 = lrelu(v0); v1 = lrelu(v1);
                v2 = lrelu(v2); v3 = lrelu(v3);
            }
            if (MODE == 2) {
                __half* C = (__half*)Cv;
                __half2 pa = make_half2(__float2half_rn(v0), __float2half_rn(v1));
                __half2 pb = make_half2(__float2half_rn(v2), __float2half_rn(v3));
                if (row < M)     *(uint32_t*)&C[(size_t)row * N + col]       = *(uint32_t*)&pa;
                if (row + 8 < M) *(uint32_t*)&C[(size_t)(row + 8) * N + col] = *(uint32_t*)&pb;
            } else {
                float* C = (float*)Cv;
                if (row < M)     *(float2*)&C[(size_t)row * N + col]       = make_float2(v0, v1);
                if (row + 8 < M) *(float2*)&C[(size_t)(row + 8) * N + col] = make_float2(v2, v3);
            }
        }
    }
}

// ---------------- launch ----------------
extern "C" void kernel_launch(void* const* d_in, const int* in_sizes, int n_in,
                              void* d_out, int out_size) {
    const float* x  = (const float*)d_in[0];
    const int*   ei = (const int*)d_in[1];     // int32 (JAX x64 disabled)
    const float* W1 = (const float*)d_in[2];
    const float* b1 = (const float*)d_in[3];
    const float* W2 = (const float*)d_in[4];
    const float* b2 = (const float*)d_in[5];
    float*       out = (float*)d_out;

    __half *zp, *tp, *hxp, *w1t, *w2t;
    cudaGetSymbolAddress((void**)&zp, g_z);
    cudaGetSymbolAddress((void**)&tp, g_t);
    cudaGetSymbolAddress((void**)&hxp, g_hx);
    cudaGetSymbolAddress((void**)&w1t, g_w1t);
    cudaGetSymbolAddress((void**)&w2t, g_w2t);

    const int SMEM = 4 * 128 * 72 * 2;   // 73728 B
    cudaFuncSetAttribute(k_gemm<128, 256, 2>, cudaFuncAttributeMaxDynamicSharedMemorySize, SMEM);
    cudaFuncSetAttribute(k_gemm<256, 128, 2>, cudaFuncAttributeMaxDynamicSharedMemorySize, SMEM);
    cudaFuncSetAttribute(k_gemm<256, 128, 0>, cudaFuncAttributeMaxDynamicSharedMemorySize, SMEM);

    const int M = N_NODES;
    const int MB = (M + 127) / 128;            // 391
    dim3 blk(256);
    dim3 grid_gather((N_NODES * 32 + 255) / 256);
    dim3 grid_g1(MB, 2);    // N=256, BN=128
    dim3 grid_g2(MB, 1);    // N=128, BN=128

    // setup covers max(N_NODES, N*D/4, L*2*D*D) elements = 1.6M
    k_setup<<<(N_NODES * D / 4 + 255) / 256, 256>>>(x, W1, W2);   // 1
    k_hist<<<(N_EDGES + 255) / 256, 256>>>(ei);                   // 2
    k_blocksum<<<N_SCAN_BLKS, SCAN_BLK>>>();                      // 3
    k_scatter2<<<N_SCAN_BLKS, SCAN_BLK>>>();                      // 4
    k_fill<<<(N_EDGES + 255) / 256, 256>>>(ei);                   // 5

    for (int l = 0; l < NUM_LAYER; l++) {
        k_gather16<<<grid_gather, blk>>>(hxp, zp);                // 6 on l=0 <- profiled
        k_gemm<128, 256, 2><<<grid_g1, blk, SMEM>>>(zp, w1t + (size_t)l * 2 * D * D,
                                                    b1 + (size_t)l * 2 * D, (void*)tp);
        if (l < NUM_LAYER - 1)
            k_gemm<256, 128, 2><<<grid_g2, blk, SMEM>>>(tp, w2t + (size_t)l * 2 * D * D,
                                                        b2 + (size_t)l * D, (void*)hxp);
        else
            k_gemm<256, 128, 0><<<grid_g2, blk, SMEM>>>(tp, w2t + (size_t)l * 2 * D * D,
                                                        b2 + (size_t)l * D, (void*)out);
    }
}

// round 14
// speedup vs baseline: 1.8944x; 1.0354x over previous
#include <cuda_runtime.h>
#include <cuda_fp16.h>
#include <cstdint>

#define N_NODES 50000
#define N_EDGES 600000
#define D 128
#define NUM_LAYER 5

#define SCAN_BLK 256
#define N_SCAN_BLKS ((N_NODES + SCAN_BLK - 1) / SCAN_BLK)   // 196

// ---------------- device scratch (allocation-free) ----------------
__device__ __half g_z[N_NODES * D];        // z = h + agg, fp16  (GEMM1 A)
__device__ __half g_t[N_NODES * 2 * D];    // hidden, fp16       (GEMM2 A)
__device__ __half g_hx[N_NODES * D];       // layer io, fp16 (gather input / GEMM2 out)
__device__ int    g_cnt[N_NODES];
__device__ int    g_rowstart[N_NODES + 1];
__device__ int    g_cursor[N_NODES];
__device__ int    g_srcs[N_EDGES];
__device__ int    g_blksum[N_SCAN_BLKS];
__device__ __half g_w1t[NUM_LAYER * 2 * D * D];  // [l][n=256][k=128] fp16
__device__ __half g_w2t[NUM_LAYER * 2 * D * D];  // [l][n=128][k=256] fp16

// ---------------- helpers ----------------
__device__ __forceinline__ float lrelu(float v) { return v >= 0.0f ? v : 0.2f * v; }

__device__ __forceinline__ void mma16(float* c, const uint32_t* a, const uint32_t* b) {
    asm volatile(
        "mma.sync.aligned.m16n8k16.row.col.f32.f16.f16.f32 "
        "{%0,%1,%2,%3}, {%4,%5,%6,%7}, {%8,%9}, {%0,%1,%2,%3};"
        : "+f"(c[0]), "+f"(c[1]), "+f"(c[2]), "+f"(c[3])
        : "r"(a[0]), "r"(a[1]), "r"(a[2]), "r"(a[3]), "r"(b[0]), "r"(b[1]));
}

__device__ __forceinline__ void ldsm_x4(uint32_t& r0, uint32_t& r1, uint32_t& r2,
                                        uint32_t& r3, uint32_t addr) {
    asm volatile("ldmatrix.sync.aligned.m8n8.x4.shared.b16 {%0,%1,%2,%3}, [%4];"
                 : "=r"(r0), "=r"(r1), "=r"(r2), "=r"(r3) : "r"(addr));
}

__device__ __forceinline__ uint32_t smem_u32(const void* p) {
    uint32_t a;
    asm("{ .reg .u64 t; cvta.to.shared.u64 t, %1; cvt.u32.u64 %0, t; }" : "=r"(a) : "l"(p));
    return a;
}
__device__ __forceinline__ void cp16(uint32_t s, const void* g) {
    asm volatile("cp.async.cg.shared.global [%0], [%1], 16;" :: "r"(s), "l"(g));
}
__device__ __forceinline__ void cp16z(uint32_t s, const void* g, int srcsz) {
    asm volatile("cp.async.cg.shared.global [%0], [%1], 16, %2;" :: "r"(s), "l"(g), "r"(srcsz));
}
#define CP_COMMIT() asm volatile("cp.async.commit_group;" ::: "memory")
#define CP_WAIT(n)  asm volatile("cp.async.wait_group %0;" :: "n"(n) : "memory")

// ------ fused setup: zero cnt, x->fp16, weight transpose+convert -----------
__global__ void k_setup(const float* __restrict__ x,
                        const float* __restrict__ W1, const float* __restrict__ W2) {
    const int HALF = NUM_LAYER * 2 * D * D;   // 163840
    int i = blockIdx.x * blockDim.x + threadIdx.x;
    if (i < N_NODES) g_cnt[i] = 0;
    if (i < N_NODES * D / 4) {
        float4 v = __ldg(&((const float4*)x)[i]);
        __half2 p0 = make_half2(__float2half_rn(v.x), __float2half_rn(v.y));
        __half2 p1 = make_half2(__float2half_rn(v.z), __float2half_rn(v.w));
        uint2 pk;
        pk.x = *(uint32_t*)&p0;
        pk.y = *(uint32_t*)&p1;
        ((uint2*)g_hx)[i] = pk;
    }
    if (i < HALF) {
        int l = i / (2 * D * D);
        int r = i % (2 * D * D);
        int n = r / D;            // 0..255
        int k = r % D;            // 0..127
        g_w1t[i] = __float2half_rn(W1[(size_t)l * 2 * D * D + (size_t)k * (2 * D) + n]);
        int n2 = r / (2 * D);     // 0..127
        int k2 = r % (2 * D);     // 0..255
        g_w2t[i] = __float2half_rn(W2[(size_t)l * 2 * D * D + (size_t)k2 * D + n2]);
    }
}

__global__ void k_hist(const int* __restrict__ ei) {
    int e = blockIdx.x * blockDim.x + threadIdx.x;
    if (e < N_EDGES) {
        int dst = ei[N_EDGES + e];
        if ((unsigned)dst < N_NODES) atomicAdd(&g_cnt[dst], 1);
    }
}

// scan phase 1: per-block sums of g_cnt
__global__ void k_blocksum() {
    __shared__ int s[SCAN_BLK];
    int tid = threadIdx.x;
    int i = blockIdx.x * SCAN_BLK + tid;
    int v = (i < N_NODES) ? g_cnt[i] : 0;
    s[tid] = v;
    __syncthreads();
#pragma unroll
    for (int off = SCAN_BLK / 2; off > 0; off >>= 1) {
        if (tid < off) s[tid] += s[tid + off];
        __syncthreads();
    }
    if (tid == 0) g_blksum[blockIdx.x] = s[0];
}

// scan phase 2: each block scans the 196 block sums redundantly, then local
// exclusive scan -> rowstart/cursor
__global__ void k_scatter2() {
    __shared__ int bs[256];
    __shared__ int s[SCAN_BLK];
    int tid = threadIdx.x;
    int bid = blockIdx.x;
    int bv = (tid < N_SCAN_BLKS) ? g_blksum[tid] : 0;
    bs[tid] = bv;
    __syncthreads();
#pragma unroll
    for (int off = 1; off < 256; off <<= 1) {
        int t = (tid >= off) ? bs[tid - off] : 0;
        __syncthreads();
        bs[tid] += t;
        __syncthreads();
    }
    int exc_blk = (bid > 0) ? bs[bid - 1] : 0;
    int i = bid * SCAN_BLK + tid;
    int v = (i < N_NODES) ? g_cnt[i] : 0;
    s[tid] = v;
    __syncthreads();
#pragma unroll
    for (int off = 1; off < SCAN_BLK; off <<= 1) {
        int t = (tid >= off) ? s[tid - off] : 0;
        __syncthreads();
        s[tid] += t;
        __syncthreads();
    }
    if (i < N_NODES) {
        int rs = exc_blk + s[tid] - v;   // exclusive
        g_rowstart[i] = rs;
        g_cursor[i]   = rs;
    }
    if (bid == N_SCAN_BLKS - 1 && tid == 255)
        g_rowstart[N_NODES] = bs[N_SCAN_BLKS - 1];
}

__global__ void k_fill(const int* __restrict__ ei) {
    int e = blockIdx.x * blockDim.x + threadIdx.x;
    if (e < N_EDGES) {
        int src = ei[e];
        int dst = ei[N_EDGES + e];
        if ((unsigned)dst < N_NODES && (unsigned)src < N_NODES) {
            int p = atomicAdd(&g_cursor[dst], 1);
            g_srcs[p] = src;
        }
    }
}

// ------ gather: 16 lanes x uint4 per edge row, 2 edges per warp-load -------
// z[n] = fp16(h[n] + sum_{src->n} h[src]), fp32 accumulation.
__device__ __forceinline__ void acc8(float* f, uint4 u) {
    float2 t;
    t = __half22float2(*(__half2*)&u.x); f[0] += t.x; f[1] += t.y;
    t = __half22float2(*(__half2*)&u.y); f[2] += t.x; f[3] += t.y;
    t = __half22float2(*(__half2*)&u.z); f[4] += t.x; f[5] += t.y;
    t = __half22float2(*(__half2*)&u.w); f[6] += t.x; f[7] += t.y;
}

__global__ void k_gather16(const __half* __restrict__ h, __half* __restrict__ z) {
    int warp = (blockIdx.x * blockDim.x + threadIdx.x) >> 5;
    int lane = threadIdx.x & 31;
    if (warp >= N_NODES) return;
    const uint4* hv = (const uint4*)h;      // 8 halfs per uint4; 16 per row
    int eo = lane >> 4;                      // edge parity handled by this half-warp
    int sl = lane & 15;                      // 16B segment within row
    int s0 = g_rowstart[warp];
    int s1 = g_rowstart[warp + 1];

    float f[8] = {0, 0, 0, 0, 0, 0, 0, 0};
    if (eo == 0) {                           // half 0 seeds with self row
        uint4 u = __ldg(&hv[(size_t)warp * 16 + sl]);
        acc8(f, u);
    }

    int e = s0;
    // 8 edges per iteration: 4 warp-loads (each covers 2 edges)
    for (; e + 8 <= s1; e += 8) {
        int i0 = g_srcs[e + 0 + eo];
        int i1 = g_srcs[e + 2 + eo];
        int i2 = g_srcs[e + 4 + eo];
        int i3 = g_srcs[e + 6 + eo];
        uint4 u0 = __ldg(&hv[(size_t)i0 * 16 + sl]);
        uint4 u1 = __ldg(&hv[(size_t)i1 * 16 + sl]);
        uint4 u2 = __ldg(&hv[(size_t)i2 * 16 + sl]);
        uint4 u3 = __ldg(&hv[(size_t)i3 * 16 + sl]);
        acc8(f, u0); acc8(f, u1); acc8(f, u2); acc8(f, u3);
    }
    // tail: up to 7 edges, 2 at a time (parity-masked)
    for (; e < s1; e += 2) {
        int idx = e + eo;
        if (idx < s1) {
            int i0 = g_srcs[idx];
            uint4 u0 = __ldg(&hv[(size_t)i0 * 16 + sl]);
            acc8(f, u0);
        }
    }

    // combine even/odd partial sums across half-warps
#pragma unroll
    for (int q = 0; q < 8; q++)
        f[q] += __shfl_xor_sync(0xFFFFFFFFu, f[q], 16);

    if (eo == 0) {
        __half2 h0 = make_half2(__float2half_rn(f[0]), __float2half_rn(f[1]));
        __half2 h1 = make_half2(__float2half_rn(f[2]), __float2half_rn(f[3]));
        __half2 h2 = make_half2(__float2half_rn(f[4]), __float2half_rn(f[5]));
        __half2 h3 = make_half2(__float2half_rn(f[6]), __float2half_rn(f[7]));
        uint4 o;
        o.x = *(uint32_t*)&h0; o.y = *(uint32_t*)&h1;
        o.z = *(uint32_t*)&h2; o.w = *(uint32_t*)&h3;
        ((uint4*)z)[(size_t)warp * 16 + sl] = o;
    }
}

// ---------------- fp16 mma.sync GEMM, cp.async staged, ldmatrix frags ------
// C = act(A[M,K] @ Bt[N,K]^T + bias). Block 128x128, 8 warps (4x2), warp 32x64.
// BK=64, 2-stage cp.async pipeline. A fp16 [M][K], Bt fp16 [N][K].
// MODE: 0 = f32 out, no act; 2 = fp16 out, leaky
template <int K, int N, int MODE>
__global__ __launch_bounds__(256) void k_gemm(
    const __half* __restrict__ A, const __half* __restrict__ Bt,
    const float* __restrict__ bias, void* __restrict__ Cv)
{
    const int M = N_NODES;
    const int BK = 64;
    const int CHUNKS = K / BK;
    const int STRIDE = 72;                  // halfs per row (64 + 8 pad), 144B
    const int TILE = 128 * STRIDE;

    extern __shared__ __half sh[];
    __half* Asb[2] = { sh, sh + TILE };
    __half* Bsb[2] = { sh + 2 * TILE, sh + 3 * TILE };

    int tid  = threadIdx.x;
    int warp = tid >> 5;
    int lane = tid & 31;
    int wm = warp >> 1;
    int wn = warp & 1;
    int g  = lane >> 2;
    int tg = lane & 3;
    int m0 = blockIdx.x * 128;
    int n0 = blockIdx.y * 128;

    uint32_t asb32[2] = { smem_u32(Asb[0]), smem_u32(Asb[1]) };
    uint32_t bsb32[2] = { smem_u32(Bsb[0]), smem_u32(Bsb[1]) };

    // ldmatrix lane offsets (in halfs, before +kk)
    int quad = lane >> 3, rin = lane & 7;
    int a_off[2], b_off[4];
#pragma unroll
    for (int mt = 0; mt < 2; mt++)
        a_off[mt] = (wm * 32 + mt * 16 + (quad & 1) * 8 + rin) * STRIDE + (quad >> 1) * 8;
#pragma unroll
    for (int ntp = 0; ntp < 4; ntp++)
        b_off[ntp] = (wn * 64 + ntp * 16 + (quad >> 1) * 8 + rin) * STRIDE + (quad & 1) * 8;

    auto stage = [&](int ch, int buf) {
        uint32_t abase = asb32[buf];
        uint32_t bbase = bsb32[buf];
#pragma unroll
        for (int j = 0; j < 4; j++) {
            int seg = tid + j * 256;
            int r   = seg >> 3;
            int c16 = seg & 7;
            int gr  = m0 + r;
            uint32_t dst = abase + (uint32_t)(r * STRIDE * 2 + c16 * 16);
            const __half* src = &A[(size_t)gr * K + ch * BK + c16 * 8];
            cp16z(dst, src, (gr < M) ? 16 : 0);
        }
#pragma unroll
        for (int j = 0; j < 4; j++) {
            int seg = tid + j * 256;
            int r   = seg >> 3;
            int c16 = seg & 7;
            uint32_t dst = bbase + (uint32_t)(r * STRIDE * 2 + c16 * 16);
            const __half* src = &Bt[(size_t)(n0 + r) * K + ch * BK + c16 * 8];
            cp16(dst, src);
        }
        CP_COMMIT();
    };

    stage(0, 0);
    if (CHUNKS > 1) stage(1, 1);

    float acc[2][8][4];
#pragma unroll
    for (int a = 0; a < 2; a++)
#pragma unroll
        for (int b = 0; b < 8; b++)
#pragma unroll
            for (int c = 0; c < 4; c++) acc[a][b][c] = 0.0f;

#pragma unroll
    for (int ch = 0; ch < CHUNKS; ch++) {
        const int buf = ch & 1;
        if (ch + 1 < CHUNKS) { CP_WAIT(1); } else { CP_WAIT(0); }
        __syncthreads();

        uint32_t abase = asb32[buf];
        uint32_t bbase = bsb32[buf];
#pragma unroll
        for (int kk = 0; kk < BK; kk += 16) {
            uint32_t af[2][4], bf[8][2];
#pragma unroll
            for (int mt = 0; mt < 2; mt++)
                ldsm_x4(af[mt][0], af[mt][1], af[mt][2], af[mt][3],
                        abase + (uint32_t)(a_off[mt] + kk) * 2);
#pragma unroll
            for (int ntp = 0; ntp < 4; ntp++)
                ldsm_x4(bf[2 * ntp][0], bf[2 * ntp][1], bf[2 * ntp + 1][0], bf[2 * ntp + 1][1],
                        bbase + (uint32_t)(b_off[ntp] + kk) * 2);
#pragma unroll
            for (int mt = 0; mt < 2; mt++)
#pragma unroll
                for (int nt = 0; nt < 8; nt++)
                    mma16(acc[mt][nt], af[mt], bf[nt]);
        }
        __syncthreads();
        if (ch + 2 < CHUNKS) stage(ch + 2, buf);
    }

    // epilogue
#pragma unroll
    for (int mt = 0; mt < 2; mt++) {
#pragma unroll
        for (int nt = 0; nt < 8; nt++) {
            int row = m0 + wm * 32 + mt * 16 + g;
            int col = n0 + wn * 64 + nt * 8 + 2 * tg;
            float b0 = __ldg(&bias[col]);
            float b1 = __ldg(&bias[col + 1]);
            float v0 = acc[mt][nt][0] + b0;
            float v1 = acc[mt][nt][1] + b1;
            float v2 = acc[mt][nt][2] + b0;
            float v3 = acc[mt][nt][3] + b1;
            if (MODE >= 1) {
                v0 = lrelu(v0); v1 = lrelu(v1);
                v2 = lrelu(v2); v3 = lrelu(v3);
            }
            if (MODE == 2) {
                __half* C = (__half*)Cv;
                __half2 pa = make_half2(__float2half_rn(v0), __float2half_rn(v1));
                __half2 pb = make_half2(__float2half_rn(v2), __float2half_rn(v3));
                if (row < M)     *(uint32_t*)&C[(size_t)row * N + col]       = *(uint32_t*)&pa;
                if (row + 8 < M) *(uint32_t*)&C[(size_t)(row + 8) * N + col] = *(uint32_t*)&pb;
            } else {
                float* C = (float*)Cv;
                if (row < M)     *(float2*)&C[(size_t)row * N + col]       = make_float2(v0, v1);
                if (row + 8 < M) *(float2*)&C[(size_t)(row + 8) * N + col] = make_float2(v2, v3);
            }
        }
    }
}

// ---------------- launch ----------------
extern "C" void kernel_launch(void* const* d_in, const int* in_sizes, int n_in,
                              void* d_out, int out_size) {
    const float* x  = (const float*)d_in[0];
    const int*   ei = (const int*)d_in[1];     // int32 (JAX x64 disabled)
    const float* W1 = (const float*)d_in[2];
    const float* b1 = (const float*)d_in[3];
    const float* W2 = (const float*)d_in[4];
    const float* b2 = (const float*)d_in[5];
    float*       out = (float*)d_out;

    __half *zp, *tp, *hxp, *w1t, *w2t;
    cudaGetSymbolAddress((void**)&zp, g_z);
    cudaGetSymbolAddress((void**)&tp, g_t);
    cudaGetSymbolAddress((void**)&hxp, g_hx);
    cudaGetSymbolAddress((void**)&w1t, g_w1t);
    cudaGetSymbolAddress((void**)&w2t, g_w2t);

    const int SMEM = 4 * 128 * 72 * 2;   // 73728 B
    cudaFuncSetAttribute(k_gemm<128, 256, 2>, cudaFuncAttributeMaxDynamicSharedMemorySize, SMEM);
    cudaFuncSetAttribute(k_gemm<256, 128, 2>, cudaFuncAttributeMaxDynamicSharedMemorySize, SMEM);
    cudaFuncSetAttribute(k_gemm<256, 128, 0>, cudaFuncAttributeMaxDynamicSharedMemorySize, SMEM);

    const int M = N_NODES;
    const int MB = (M + 127) / 128;            // 391
    dim3 blk(256);
    dim3 grid_gather((N_NODES * 32 + 255) / 256);
    dim3 grid_g1(MB, 2);    // N=256, BN=128
    dim3 grid_g2(MB, 1);    // N=128, BN=128

    k_setup<<<(N_NODES * D / 4 + 255) / 256, 256>>>(x, W1, W2);   // 1
    k_hist<<<(N_EDGES + 255) / 256, 256>>>(ei);                   // 2
    k_blocksum<<<N_SCAN_BLKS, SCAN_BLK>>>();                      // 3
    k_scatter2<<<N_SCAN_BLKS, SCAN_BLK>>>();                      // 4
    k_fill<<<(N_EDGES + 255) / 256, 256>>>(ei);                   // 5

    for (int l = 0; l < NUM_LAYER; l++) {
        k_gather16<<<grid_gather, blk>>>(hxp, zp);
        k_gemm<128, 256, 2><<<grid_g1, blk, SMEM>>>(zp, w1t + (size_t)l * 2 * D * D,
                                                    b1 + (size_t)l * 2 * D, (void*)tp);
        if (l < NUM_LAYER - 1)
            k_gemm<256, 128, 2><<<grid_g2, blk, SMEM>>>(tp, w2t + (size_t)l * 2 * D * D,
                                                        b2 + (size_t)l * D, (void*)hxp);
        else
            k_gemm<256, 128, 0><<<grid_g2, blk, SMEM>>>(tp, w2t + (size_t)l * 2 * D * D,
                                                        b2 + (size_t)l * D, (void*)out);
    }
}

// round 17
// speedup vs baseline: 2.0980x; 1.1075x over previous
#include <cuda_runtime.h>
#include <cuda_fp16.h>
#include <cstdint>

#define N_NODES 50000
#define N_EDGES 600000
#define D 128
#define NUM_LAYER 5

#define SCAN_BLK 256
#define N_SCAN_BLKS ((N_NODES + SCAN_BLK - 1) / SCAN_BLK)   // 196

// ---------------- device scratch (allocation-free) ----------------
__device__ __half g_z[N_NODES * D];        // z = h + agg, fp16  (MLP input)
__device__ __half g_hx[N_NODES * D];       // layer io, fp16 (gather input / MLP out)
__device__ int    g_cnt[N_NODES];
__device__ int    g_rowstart[N_NODES + 1];
__device__ int    g_cursor[N_NODES];
__device__ int    g_srcs[N_EDGES];
__device__ int    g_blksum[N_SCAN_BLKS];
__device__ __half g_w1t[NUM_LAYER * 2 * D * D];  // [l][n=256][k=128] fp16
__device__ __half g_w2t[NUM_LAYER * 2 * D * D];  // [l][n=128][k=256] fp16

// ---------------- helpers ----------------
__device__ __forceinline__ float lrelu(float v) { return v >= 0.0f ? v : 0.2f * v; }

__device__ __forceinline__ void mma16(float* c, const uint32_t* a, const uint32_t* b) {
    asm volatile(
        "mma.sync.aligned.m16n8k16.row.col.f32.f16.f16.f32 "
        "{%0,%1,%2,%3}, {%4,%5,%6,%7}, {%8,%9}, {%0,%1,%2,%3};"
        : "+f"(c[0]), "+f"(c[1]), "+f"(c[2]), "+f"(c[3])
        : "r"(a[0]), "r"(a[1]), "r"(a[2]), "r"(a[3]), "r"(b[0]), "r"(b[1]));
}

__device__ __forceinline__ void ldsm_x4(uint32_t& r0, uint32_t& r1, uint32_t& r2,
                                        uint32_t& r3, uint32_t addr) {
    asm volatile("ldmatrix.sync.aligned.m8n8.x4.shared.b16 {%0,%1,%2,%3}, [%4];"
                 : "=r"(r0), "=r"(r1), "=r"(r2), "=r"(r3) : "r"(addr));
}

__device__ __forceinline__ uint32_t smem_u32(const void* p) {
    uint32_t a;
    asm("{ .reg .u64 t; cvta.to.shared.u64 t, %1; cvt.u32.u64 %0, t; }" : "=r"(a) : "l"(p));
    return a;
}
__device__ __forceinline__ void cp16(uint32_t s, const void* g) {
    asm volatile("cp.async.cg.shared.global [%0], [%1], 16;" :: "r"(s), "l"(g));
}
__device__ __forceinline__ void cp16z(uint32_t s, const void* g, int srcsz) {
    asm volatile("cp.async.cg.shared.global [%0], [%1], 16, %2;" :: "r"(s), "l"(g), "r"(srcsz));
}
#define CP_COMMIT() asm volatile("cp.async.commit_group;" ::: "memory")
#define CP_WAIT(n)  asm volatile("cp.async.wait_group %0;" :: "n"(n) : "memory")

// ------ fused setup: zero cnt, x->fp16, weight transpose+convert -----------
__global__ void k_setup(const float* __restrict__ x,
                        const float* __restrict__ W1, const float* __restrict__ W2) {
    const int HALF = NUM_LAYER * 2 * D * D;   // 163840
    int i = blockIdx.x * blockDim.x + threadIdx.x;
    if (i < N_NODES) g_cnt[i] = 0;
    if (i < N_NODES * D / 4) {
        float4 v = __ldg(&((const float4*)x)[i]);
        __half2 p0 = make_half2(__float2half_rn(v.x), __float2half_rn(v.y));
        __half2 p1 = make_half2(__float2half_rn(v.z), __float2half_rn(v.w));
        uint2 pk;
        pk.x = *(uint32_t*)&p0;
        pk.y = *(uint32_t*)&p1;
        ((uint2*)g_hx)[i] = pk;
    }
    if (i < HALF) {
        int l = i / (2 * D * D);
        int r = i % (2 * D * D);
        int n = r / D;            // 0..255
        int k = r % D;            // 0..127
        g_w1t[i] = __float2half_rn(W1[(size_t)l * 2 * D * D + (size_t)k * (2 * D) + n]);
        int n2 = r / (2 * D);     // 0..127
        int k2 = r % (2 * D);     // 0..255
        g_w2t[i] = __float2half_rn(W2[(size_t)l * 2 * D * D + (size_t)k2 * D + n2]);
    }
}

__global__ void k_hist(const int* __restrict__ ei) {
    int e = blockIdx.x * blockDim.x + threadIdx.x;
    if (e < N_EDGES) {
        int dst = ei[N_EDGES + e];
        if ((unsigned)dst < N_NODES) atomicAdd(&g_cnt[dst], 1);
    }
}

__global__ void k_blocksum() {
    __shared__ int s[SCAN_BLK];
    int tid = threadIdx.x;
    int i = blockIdx.x * SCAN_BLK + tid;
    int v = (i < N_NODES) ? g_cnt[i] : 0;
    s[tid] = v;
    __syncthreads();
#pragma unroll
    for (int off = SCAN_BLK / 2; off > 0; off >>= 1) {
        if (tid < off) s[tid] += s[tid + off];
        __syncthreads();
    }
    if (tid == 0) g_blksum[blockIdx.x] = s[0];
}

__global__ void k_scatter2() {
    __shared__ int bs[256];
    __shared__ int s[SCAN_BLK];
    int tid = threadIdx.x;
    int bid = blockIdx.x;
    int bv = (tid < N_SCAN_BLKS) ? g_blksum[tid] : 0;
    bs[tid] = bv;
    __syncthreads();
#pragma unroll
    for (int off = 1; off < 256; off <<= 1) {
        int t = (tid >= off) ? bs[tid - off] : 0;
        __syncthreads();
        bs[tid] += t;
        __syncthreads();
    }
    int exc_blk = (bid > 0) ? bs[bid - 1] : 0;
    int i = bid * SCAN_BLK + tid;
    int v = (i < N_NODES) ? g_cnt[i] : 0;
    s[tid] = v;
    __syncthreads();
#pragma unroll
    for (int off = 1; off < SCAN_BLK; off <<= 1) {
        int t = (tid >= off) ? s[tid - off] : 0;
        __syncthreads();
        s[tid] += t;
        __syncthreads();
    }
    if (i < N_NODES) {
        int rs = exc_blk + s[tid] - v;   // exclusive
        g_rowstart[i] = rs;
        g_cursor[i]   = rs;
    }
    if (bid == N_SCAN_BLKS - 1 && tid == 255)
        g_rowstart[N_NODES] = bs[N_SCAN_BLKS - 1];
}

__global__ void k_fill(const int* __restrict__ ei) {
    int e = blockIdx.x * blockDim.x + threadIdx.x;
    if (e < N_EDGES) {
        int src = ei[e];
        int dst = ei[N_EDGES + e];
        if ((unsigned)dst < N_NODES && (unsigned)src < N_NODES) {
            int p = atomicAdd(&g_cursor[dst], 1);
            g_srcs[p] = src;
        }
    }
}

// ------ gather: 16 lanes x uint4 per edge row, 2 edges per warp-load -------
__device__ __forceinline__ void acc8(float* f, uint4 u) {
    float2 t;
    t = __half22float2(*(__half2*)&u.x); f[0] += t.x; f[1] += t.y;
    t = __half22float2(*(__half2*)&u.y); f[2] += t.x; f[3] += t.y;
    t = __half22float2(*(__half2*)&u.z); f[4] += t.x; f[5] += t.y;
    t = __half22float2(*(__half2*)&u.w); f[6] += t.x; f[7] += t.y;
}

__global__ void k_gather16(const __half* __restrict__ h, __half* __restrict__ z) {
    int warp = (blockIdx.x * blockDim.x + threadIdx.x) >> 5;
    int lane = threadIdx.x & 31;
    if (warp >= N_NODES) return;
    const uint4* hv = (const uint4*)h;      // 8 halfs per uint4; 16 per row
    int eo = lane >> 4;                      // edge parity for this half-warp
    int sl = lane & 15;                      // 16B segment within row
    int s0 = g_rowstart[warp];
    int s1 = g_rowstart[warp + 1];

    float f[8] = {0, 0, 0, 0, 0, 0, 0, 0};
    if (eo == 0) {
        uint4 u = __ldg(&hv[(size_t)warp * 16 + sl]);
        acc8(f, u);
    }

    int e = s0;
    for (; e + 8 <= s1; e += 8) {
        int i0 = g_srcs[e + 0 + eo];
        int i1 = g_srcs[e + 2 + eo];
        int i2 = g_srcs[e + 4 + eo];
        int i3 = g_srcs[e + 6 + eo];
        uint4 u0 = __ldg(&hv[(size_t)i0 * 16 + sl]);
        uint4 u1 = __ldg(&hv[(size_t)i1 * 16 + sl]);
        uint4 u2 = __ldg(&hv[(size_t)i2 * 16 + sl]);
        uint4 u3 = __ldg(&hv[(size_t)i3 * 16 + sl]);
        acc8(f, u0); acc8(f, u1); acc8(f, u2); acc8(f, u3);
    }
    for (; e < s1; e += 2) {
        int idx = e + eo;
        if (idx < s1) {
            int i0 = g_srcs[idx];
            uint4 u0 = __ldg(&hv[(size_t)i0 * 16 + sl]);
            acc8(f, u0);
        }
    }

#pragma unroll
    for (int q = 0; q < 8; q++)
        f[q] += __shfl_xor_sync(0xFFFFFFFFu, f[q], 16);

    if (eo == 0) {
        __half2 h0 = make_half2(__float2half_rn(f[0]), __float2half_rn(f[1]));
        __half2 h1 = make_half2(__float2half_rn(f[2]), __float2half_rn(f[3]));
        __half2 h2 = make_half2(__float2half_rn(f[4]), __float2half_rn(f[5]));
        __half2 h3 = make_half2(__float2half_rn(f[6]), __float2half_rn(f[7]));
        uint4 o;
        o.x = *(uint32_t*)&h0; o.y = *(uint32_t*)&h1;
        o.z = *(uint32_t*)&h2; o.w = *(uint32_t*)&h3;
        ((uint4*)z)[(size_t)warp * 16 + sl] = o;
    }
}

// --------- fused MLP: out = act2(lrelu(Z@W1^T + b1) @ W2^T + b2) -----------
// 512 threads (16 warps), grid 391. Hidden tensor lives in SMEM only.
// Phase A: GEMM1 128x256x128 (warp tile 32x64, 4x4 warps).
// Phase B: GEMM2 128x128x256 (warp tile 32x32), W2 streamed BK=64 double-buf.
// SMEM (halfs): As 128x136 | B1 256x136 | T 128x264 | B2 2x128x72 = 208896 B
// MODE: 2 = fp16 out + leaky; 0 = f32 out, no act
template <int MODE>
__global__ __launch_bounds__(512) void k_mlp(
    const __half* __restrict__ Z, const __half* __restrict__ B1t,
    const float* __restrict__ bias1, const __half* __restrict__ B2t,
    const float* __restrict__ bias2, void* __restrict__ Cv)
{
    const int M = N_NODES;
    const int SA = 136, ST = 264, SB2 = 72;
    const int OFF_AS = 0;
    const int OFF_B1 = 17408;
    const int OFF_T  = 52224;
    const int OFF_B2 = 86016;          // two bufs of 9216

    extern __shared__ __half sh[];
    uint32_t sb = smem_u32(sh);
    uint32_t asb = sb + OFF_AS * 2;
    uint32_t b1b = sb + OFF_B1 * 2;
    uint32_t tb  = sb + OFF_T  * 2;
    uint32_t b2b[2] = { sb + OFF_B2 * 2, sb + (OFF_B2 + 9216) * 2 };
    __half* T = sh + OFF_T;

    int tid  = threadIdx.x;
    int warp = tid >> 5;
    int lane = tid & 31;
    int wm = warp >> 2;        // 0..3
    int wn = warp & 3;         // 0..3
    int g  = lane >> 2;        // 0..7
    int tg = lane & 3;         // 0..3
    int quad = lane >> 3, rin = lane & 7;
    int m0 = blockIdx.x * 128;

    // W2 chunk staging: 128 rows x 64 halfs = 1024 x 16B segs (2 per thread)
    auto stage2 = [&](int ch, int buf) {
#pragma unroll
        for (int j = 0; j < 2; j++) {
            int seg = tid + j * 512;   // 0..1023
            int r = seg >> 3;          // 0..127
            int c = seg & 7;           // 0..7
            cp16(b2b[buf] + (uint32_t)(r * SB2 + c * 8) * 2,
                 &B2t[(size_t)r * 256 + ch * 64 + c * 8]);
        }
        CP_COMMIT();
    };

    // ---- stage As (128 rows x 128 halfs = 2048 segs) ----
#pragma unroll
    for (int j = 0; j < 4; j++) {
        int seg = tid + j * 512;   // 0..2047
        int r = seg >> 4;          // 0..127
        int c = seg & 15;          // 0..15
        int gr = m0 + r;
        cp16z(asb + (uint32_t)(r * SA + c * 8) * 2,
              &Z[(size_t)gr * 128 + c * 8], (gr < M) ? 16 : 0);
    }
    // ---- stage B1 (256 rows x 128 halfs = 4096 segs) ----
#pragma unroll
    for (int j = 0; j < 8; j++) {
        int seg = tid + j * 512;   // 0..4095
        int r = seg >> 4;          // 0..255
        int c = seg & 15;          // 0..15
        cp16(b1b + (uint32_t)(r * SA + c * 8) * 2, &B1t[(size_t)r * 128 + c * 8]);
    }
    CP_COMMIT();                   // G0
    stage2(0, 0);                  // G1
    stage2(1, 1);                  // G2
    CP_WAIT(2);                    // G0 complete (As + B1 ready)
    __syncthreads();

    // ---- phase A: GEMM1 ----
    int a1_off[2], b1_off[4];
#pragma unroll
    for (int mt = 0; mt < 2; mt++)
        a1_off[mt] = (wm * 32 + mt * 16 + (quad & 1) * 8 + rin) * SA + (quad >> 1) * 8;
#pragma unroll
    for (int ntp = 0; ntp < 4; ntp++)
        b1_off[ntp] = (wn * 64 + ntp * 16 + (quad >> 1) * 8 + rin) * SA + (quad & 1) * 8;

    {
        float acc[2][8][4];
#pragma unroll
        for (int a = 0; a < 2; a++)
#pragma unroll
            for (int b = 0; b < 8; b++)
#pragma unroll
                for (int c = 0; c < 4; c++) acc[a][b][c] = 0.0f;

#pragma unroll
        for (int kk = 0; kk < 128; kk += 16) {
            uint32_t af[2][4], bf[8][2];
#pragma unroll
            for (int mt = 0; mt < 2; mt++)
                ldsm_x4(af[mt][0], af[mt][1], af[mt][2], af[mt][3],
                        asb + (uint32_t)(a1_off[mt] + kk) * 2);
#pragma unroll
            for (int ntp = 0; ntp < 4; ntp++)
                ldsm_x4(bf[2 * ntp][0], bf[2 * ntp][1], bf[2 * ntp + 1][0], bf[2 * ntp + 1][1],
                        b1b + (uint32_t)(b1_off[ntp] + kk) * 2);
#pragma unroll
            for (int mt = 0; mt < 2; mt++)
#pragma unroll
                for (int nt = 0; nt < 8; nt++)
                    mma16(acc[mt][nt], af[mt], bf[nt]);
        }

        // bias1 + lrelu -> T (smem, fp16)
#pragma unroll
        for (int mt = 0; mt < 2; mt++) {
#pragma unroll
            for (int nt = 0; nt < 8; nt++) {
                int row = wm * 32 + mt * 16 + g;
                int col = wn * 64 + nt * 8 + 2 * tg;
                float b0 = __ldg(&bias1[col]);
                float b1v = __ldg(&bias1[col + 1]);
                float v0 = lrelu(acc[mt][nt][0] + b0);
                float v1 = lrelu(acc[mt][nt][1] + b1v);
                float v2 = lrelu(acc[mt][nt][2] + b0);
                float v3 = lrelu(acc[mt][nt][3] + b1v);
                __half2 pa = make_half2(__float2half_rn(v0), __float2half_rn(v1));
                __half2 pb = make_half2(__float2half_rn(v2), __float2half_rn(v3));
                *(uint32_t*)&T[row * ST + col]       = *(uint32_t*)&pa;
                *(uint32_t*)&T[(row + 8) * ST + col] = *(uint32_t*)&pb;
            }
        }
    }
    __syncthreads();

    // ---- phase B: GEMM2 (A = T in smem, W2 streamed) ----
    int a2_off[2], b2_off[2];
#pragma unroll
    for (int mt = 0; mt < 2; mt++)
        a2_off[mt] = (wm * 32 + mt * 16 + (quad & 1) * 8 + rin) * ST + (quad >> 1) * 8;
#pragma unroll
    for (int ntp = 0; ntp < 2; ntp++)
        b2_off[ntp] = (wn * 32 + ntp * 16 + (quad >> 1) * 8 + rin) * SB2 + (quad & 1) * 8;

    float acc2[2][4][4];
#pragma unroll
    for (int a = 0; a < 2; a++)
#pragma unroll
        for (int b = 0; b < 4; b++)
#pragma unroll
            for (int c = 0; c < 4; c++) acc2[a][b][c] = 0.0f;

#pragma unroll
    for (int ch = 0; ch < 4; ch++) {
        if (ch < 3) { CP_WAIT(1); } else { CP_WAIT(0); }
        __syncthreads();
        uint32_t bbase = b2b[ch & 1];
#pragma unroll
        for (int kk = 0; kk < 64; kk += 16) {
            uint32_t af[2][4], bf[4][2];
#pragma unroll
            for (int mt = 0; mt < 2; mt++)
                ldsm_x4(af[mt][0], af[mt][1], af[mt][2], af[mt][3],
                        tb + (uint32_t)(a2_off[mt] + ch * 64 + kk) * 2);
#pragma unroll
            for (int ntp = 0; ntp < 2; ntp++)
                ldsm_x4(bf[2 * ntp][0], bf[2 * ntp][1], bf[2 * ntp + 1][0], bf[2 * ntp + 1][1],
                        bbase + (uint32_t)(b2_off[ntp] + kk) * 2);
#pragma unroll
            for (int mt = 0; mt < 2; mt++)
#pragma unroll
                for (int nt = 0; nt < 4; nt++)
                    mma16(acc2[mt][nt], af[mt], bf[nt]);
        }
        __syncthreads();
        if (ch + 2 < 4) stage2(ch + 2, ch & 1);
    }

    // ---- epilogue ----
#pragma unroll
    for (int mt = 0; mt < 2; mt++) {
#pragma unroll
        for (int nt = 0; nt < 4; nt++) {
            int row = m0 + wm * 32 + mt * 16 + g;
            int col = wn * 32 + nt * 8 + 2 * tg;
            float b0 = __ldg(&bias2[col]);
            float b1v = __ldg(&bias2[col + 1]);
            float v0 = acc2[mt][nt][0] + b0;
            float v1 = acc2[mt][nt][1] + b1v;
            float v2 = acc2[mt][nt][2] + b0;
            float v3 = acc2[mt][nt][3] + b1v;
            if (MODE == 2) {
                v0 = lrelu(v0); v1 = lrelu(v1);
                v2 = lrelu(v2); v3 = lrelu(v3);
                __half* C = (__half*)Cv;
                __half2 pa = make_half2(__float2half_rn(v0), __float2half_rn(v1));
                __half2 pb = make_half2(__float2half_rn(v2), __float2half_rn(v3));
                if (row < M)     *(uint32_t*)&C[(size_t)row * 128 + col]       = *(uint32_t*)&pa;
                if (row + 8 < M) *(uint32_t*)&C[(size_t)(row + 8) * 128 + col] = *(uint32_t*)&pb;
            } else {
                float* C = (float*)Cv;
                if (row < M)     *(float2*)&C[(size_t)row * 128 + col]       = make_float2(v0, v1);
                if (row + 8 < M) *(float2*)&C[(size_t)(row + 8) * 128 + col] = make_float2(v2, v3);
            }
        }
    }
}

// ---------------- launch ----------------
extern "C" void kernel_launch(void* const* d_in, const int* in_sizes, int n_in,
                              void* d_out, int out_size) {
    const float* x  = (const float*)d_in[0];
    const int*   ei = (const int*)d_in[1];     // int32 (JAX x64 disabled)
    const float* W1 = (const float*)d_in[2];
    const float* b1 = (const float*)d_in[3];
    const float* W2 = (const float*)d_in[4];
    const float* b2 = (const float*)d_in[5];
    float*       out = (float*)d_out;

    __half *zp, *hxp, *w1t, *w2t;
    cudaGetSymbolAddress((void**)&zp, g_z);
    cudaGetSymbolAddress((void**)&hxp, g_hx);
    cudaGetSymbolAddress((void**)&w1t, g_w1t);
    cudaGetSymbolAddress((void**)&w2t, g_w2t);

    const int SMEM = 104448 * 2;   // 208896 B
    cudaFuncSetAttribute(k_mlp<2>, cudaFuncAttributeMaxDynamicSharedMemorySize, SMEM);
    cudaFuncSetAttribute(k_mlp<0>, cudaFuncAttributeMaxDynamicSharedMemorySize, SMEM);

    const int MB = (N_NODES + 127) / 128;      // 391
    dim3 grid_gather((N_NODES * 32 + 255) / 256);

    k_setup<<<(N_NODES * D / 4 + 255) / 256, 256>>>(x, W1, W2);
    k_hist<<<(N_EDGES + 255) / 256, 256>>>(ei);
    k_blocksum<<<N_SCAN_BLKS, SCAN_BLK>>>();
    k_scatter2<<<N_SCAN_BLKS, SCAN_BLK>>>();
    k_fill<<<(N_EDGES + 255) / 256, 256>>>(ei);

    for (int l = 0; l < NUM_LAYER; l++) {
        k_gather16<<<grid_gather, 256>>>(hxp, zp);
        const __half* w1l = w1t + (size_t)l * 2 * D * D;
        const __half* w2l = w2t + (size_t)l * 2 * D * D;
        const float*  b1l = b1 + (size_t)l * 2 * D;
        const float*  b2l = b2 + (size_t)l * D;
        if (l < NUM_LAYER - 1)
            k_mlp<2><<<MB, 512, SMEM>>>(zp, w1l, b1l, w2l, b2l, (void*)hxp);
        else
            k_mlp<0><<<MB, 512, SMEM>>>(zp, w1l, b1l, w2l, b2l, (void*)out);
    }
}